// round 3
// baseline (speedup 1.0000x reference)
#include <cuda_runtime.h>
#include <cuda_bf16.h>
#include <math.h>

// Problem constants
#define Bsz 4096
#define Ssz 1536
#define Lsz 2048
#define Hsz 1024
#define MINTOK 460                     // int(0.3*1536)
#define NEEDFIX_THRESH (Ssz - MINTOK)  // 1076

// ---------------- scratch (device globals; no allocations allowed) ----------
__device__ float g_A [(size_t)Bsz * Lsz];
__device__ float g_Bf[(size_t)Bsz * Lsz];
__device__ float g_C1[(size_t)Bsz * Hsz];
__device__ float g_C2[(size_t)Bsz * Hsz];
__device__ float g_C3[(size_t)Bsz * Hsz];
__device__ float g_D1[(size_t)Bsz * (Hsz/2)];
__device__ float g_D2[(size_t)Bsz * (Hsz/4)];

#define CCH 16
__device__ double g_p1[CCH * Lsz];
__device__ double g_p2[CCH * Lsz];
__device__ double g_p3[CCH * Lsz];
__device__ double g_S1[Lsz], g_S2[Lsz], g_S3[Lsz];
__device__ float  g_adj[Lsz];
__device__ float  g_rowEnt[Bsz], g_rowDiff[Bsz];
__device__ double g_cons[1];

// ---------------- GEMM: C[M,N] = A[M,K] @ W[N,K]^T + bias[N] ----------------
// Near-exact accumulation: fp32 FFMA within each BK=16 chunk, folded into a
// double accumulator per output. Dot-product error ~1e-8 relative -> the
// diff vs the reference collapses to the reference's own fp32 error.
// 128(M) x 64(N) block tile, 8x4 per thread, 256 threads, 1 CTA/SM.
__global__ void __launch_bounds__(256, 1)
sgemm_nt(const float* __restrict__ A, const float* __restrict__ W,
         const float* __restrict__ bias, float* __restrict__ C,
         int M, int N, int K)
{
    constexpr int BK = 16;
    __shared__ float As[BK][128 + 4];
    __shared__ float Bs[BK][64 + 4];
    const int tid = threadIdx.x;
    const int bm = blockIdx.y * 128;
    const int bn = blockIdx.x * 64;
    const int ty = tid >> 4;            // 0..15 (M groups of 8)
    const int tx = tid & 15;            // 0..15 (N groups of 4)
    const int tr = ty << 3;
    const int tc = tx << 2;
    const int arow  = tid >> 1;         // 0..127
    const int ahalf = (tid & 1) << 3;   // 0 or 8
    const int wrow  = tid >> 2;         // 0..63
    const int wq    = (tid & 3) << 2;   // 0,4,8,12

    const float* Ap = A + (size_t)(bm + arow) * K + ahalf;
    const float* Wp = W + (size_t)(bn + wrow) * K + wq;

    double dacc[8][4];
#pragma unroll
    for (int i = 0; i < 8; i++)
#pragma unroll
        for (int j = 0; j < 4; j++) dacc[i][j] = 0.0;

    for (int k0 = 0; k0 < K; k0 += BK) {
        float4 a0 = *(const float4*)(Ap + k0);
        float4 a1 = *(const float4*)(Ap + k0 + 4);
        float4 b0 = *(const float4*)(Wp + k0);
        __syncthreads();
        As[ahalf + 0][arow] = a0.x; As[ahalf + 1][arow] = a0.y;
        As[ahalf + 2][arow] = a0.z; As[ahalf + 3][arow] = a0.w;
        As[ahalf + 4][arow] = a1.x; As[ahalf + 5][arow] = a1.y;
        As[ahalf + 6][arow] = a1.z; As[ahalf + 7][arow] = a1.w;
        Bs[wq + 0][wrow] = b0.x; Bs[wq + 1][wrow] = b0.y;
        Bs[wq + 2][wrow] = b0.z; Bs[wq + 3][wrow] = b0.w;
        __syncthreads();

        float facc[8][4];
#pragma unroll
        for (int i = 0; i < 8; i++)
#pragma unroll
            for (int j = 0; j < 4; j++) facc[i][j] = 0.f;

#pragma unroll
        for (int k = 0; k < BK; k++) {
            float a[8], b[4];
            *(float4*)(a)     = *(const float4*)(&As[k][tr]);
            *(float4*)(a + 4) = *(const float4*)(&As[k][tr + 4]);
            *(float4*)(b)     = *(const float4*)(&Bs[k][tc]);
#pragma unroll
            for (int i = 0; i < 8; i++)
#pragma unroll
                for (int j = 0; j < 4; j++)
                    facc[i][j] = fmaf(a[i], b[j], facc[i][j]);
        }
#pragma unroll
        for (int i = 0; i < 8; i++)
#pragma unroll
            for (int j = 0; j < 4; j++) dacc[i][j] += (double)facc[i][j];
    }

    float bj[4];
#pragma unroll
    for (int j = 0; j < 4; j++) bj[j] = bias[bn + tc + j];
#pragma unroll
    for (int i = 0; i < 8; i++) {
        float* Cp = C + (size_t)(bm + tr + i) * N + bn + tc;
        float4 v = make_float4(__fadd_rn((float)dacc[i][0], bj[0]),
                               __fadd_rn((float)dacc[i][1], bj[1]),
                               __fadd_rn((float)dacc[i][2], bj[2]),
                               __fadd_rn((float)dacc[i][3], bj[3]));
        *(float4*)Cp = v;
    }
}

// ---------------- LN of padded int input -> X0 (double-precise stats) -------
__global__ void ln_input_kernel(const int* __restrict__ ids,
                                const float* __restrict__ gam,
                                const float* __restrict__ bet,
                                float* __restrict__ out)
{
    __shared__ float s[Lsz];
    __shared__ double red[256];
    const int r = blockIdx.x, tid = threadIdx.x;
    for (int j = tid; j < Lsz; j += 256)
        s[j] = (j < Ssz) ? (float)ids[(size_t)r * Ssz + j] : 0.f;
    __syncthreads();
    double p = 0.0;
    for (int j = tid; j < Lsz; j += 256) p += (double)s[j];
    red[tid] = p; __syncthreads();
    for (int o = 128; o > 0; o >>= 1) { if (tid < o) red[tid] += red[tid + o]; __syncthreads(); }
    const double mean = red[0] / (double)Lsz;
    const float  mf   = (float)mean;
    __syncthreads();
    double v = 0.0;
    for (int j = tid; j < Lsz; j += 256) { double d = (double)s[j] - mean; v += d * d; }
    red[tid] = v; __syncthreads();
    for (int o = 128; o > 0; o >>= 1) { if (tid < o) red[tid] += red[tid + o]; __syncthreads(); }
    const float vf  = (float)(red[0] / (double)Lsz);
    const float arg = __fadd_rn(vf, 1e-5f);
    const float rs  = (float)(1.0 / sqrt((double)arg));
    for (int j = tid; j < Lsz; j += 256) {
        float t = __fmul_rn(__fmul_rn(__fsub_rn(s[j], mf), rs), gam[j]);
        out[(size_t)r * Lsz + j] = __fadd_rn(t, bet[j]);
    }
}

// ---------------- LN + exact GELU (+ optional residual), per row ------------
__global__ void ln_gelu_kernel(const float* __restrict__ in,
                               const float* __restrict__ gam,
                               const float* __restrict__ bet,
                               const float* __restrict__ res,
                               float* __restrict__ out, int n)
{
    __shared__ float s[Lsz];
    __shared__ double red[256];
    const int r = blockIdx.x, tid = threadIdx.x;
    for (int j = tid; j < n; j += 256) s[j] = in[(size_t)r * n + j];
    __syncthreads();
    double p = 0.0;
    for (int j = tid; j < n; j += 256) p += (double)s[j];
    red[tid] = p; __syncthreads();
    for (int o = 128; o > 0; o >>= 1) { if (tid < o) red[tid] += red[tid + o]; __syncthreads(); }
    const double mean = red[0] / (double)n;
    const float  mf   = (float)mean;
    __syncthreads();
    double v = 0.0;
    for (int j = tid; j < n; j += 256) { double d = (double)s[j] - mean; v += d * d; }
    red[tid] = v; __syncthreads();
    for (int o = 128; o > 0; o >>= 1) { if (tid < o) red[tid] += red[tid + o]; __syncthreads(); }
    const float vf  = (float)(red[0] / (double)n);
    const float arg = __fadd_rn(vf, 1e-5f);
    const float rs  = (float)(1.0 / sqrt((double)arg));
    for (int j = tid; j < n; j += 256) {
        float x = __fadd_rn(__fmul_rn(__fmul_rn(__fsub_rn(s[j], mf), rs), gam[j]), bet[j]);
        double u = (double)x * 0.7071067811865475244;
        float e = (float)erf(u);
        float ge = __fmul_rn(__fmul_rn(x, __fadd_rn(e, 1.f)), 0.5f);
        float o = res ? __fadd_rn(ge, res[(size_t)r * n + j]) : ge;
        out[(size_t)r * n + j] = o;
    }
}

// ---------------- mu -> z = sigmoid(clip(mu,-5,5)), exact -------------------
__global__ void sigmoid_kernel(const float* __restrict__ mu, float* __restrict__ z)
{
    size_t i = (size_t)blockIdx.x * 256 + threadIdx.x;
    if (i < (size_t)Bsz * Lsz) {
        float m = mu[i];
        m = fminf(5.f, fmaxf(-5.f, m));
        z[i] = (float)(1.0 / (1.0 + exp(-(double)m)));
    }
}

// ---------------- column stats ----------------------------------------------
__global__ void colstats_kernel(const float* __restrict__ Z)
{
    const int j  = blockIdx.x * 256 + threadIdx.x;
    const int ch = blockIdx.y;
    const int r0 = ch * (Bsz / CCH);
    const bool hasN = (j < Lsz - 1);
    double s1 = 0, s2 = 0, s3 = 0;
    for (int r = r0; r < r0 + (Bsz / CCH); ++r) {
        float z  = Z[(size_t)r * Lsz + j];
        float zn = hasN ? Z[(size_t)r * Lsz + j + 1] : 0.f;
        s1 += (double)z;
        s2 += (double)z * (double)z;
        s3 += (double)z * (double)zn;
    }
    g_p1[ch * Lsz + j] = s1;
    g_p2[ch * Lsz + j] = s2;
    g_p3[ch * Lsz + j] = s3;
}

__global__ void colcombine_kernel()
{
    const int j = blockIdx.x * 256 + threadIdx.x;
    double s1 = 0, s2 = 0, s3 = 0;
    for (int c = 0; c < CCH; c++) {
        s1 += g_p1[c * Lsz + j];
        s2 += g_p2[c * Lsz + j];
        s3 += g_p3[c * Lsz + j];
    }
    g_S1[j] = s1; g_S2[j] = s2; g_S3[j] = s3;
}

// ---------------- adj (corr>0.5) + consistency term -------------------------
__global__ void adjcons_kernel(const float* __restrict__ fe)
{
    __shared__ double red[256];
    const int tid = threadIdx.x;
    double cons = 0.0;
    for (int j = tid; j < Lsz; j += 256) {
        double m = g_S1[j] / (double)Bsz;
        cons += fabs(m - (double)fe[j]);
        if (j < Lsz - 1) {
            double cov = g_S3[j] - g_S1[j] * g_S1[j + 1] / (double)Bsz;
            double v1  = g_S2[j]     - g_S1[j]     * g_S1[j]     / (double)Bsz;
            double v2  = g_S2[j + 1] - g_S1[j + 1] * g_S1[j + 1] / (double)Bsz;
            double den = v1 * v2;
            float a = 0.f;
            if (den > 0.0 && cov / sqrt(den) > 0.5) a = 1.f;
            g_adj[j] = a;
        }
    }
    red[tid] = cons; __syncthreads();
    for (int o = 128; o > 0; o >>= 1) { if (tid < o) red[tid] += red[tid + o]; __syncthreads(); }
    if (tid == 0) g_cons[0] = red[0];
}

// ---------------- per-row mask / top-k / outputs -----------------------------
__global__ void __launch_bounds__(256)
rowmask_kernel(const float* __restrict__ Z, const int* __restrict__ ids,
               float* __restrict__ outG, float* __restrict__ outZ)
{
    __shared__ float zs[Lsz];
    __shared__ float redf[256];
    __shared__ int   redi[256];
    __shared__ unsigned int hist[256];
    __shared__ unsigned int sh_prefix;
    __shared__ int sh_k;
    __shared__ int wsum[8];

    const int r = blockIdx.x, tid = threadIdx.x;
    for (int j = tid; j < Lsz; j += 256) zs[j] = Z[(size_t)r * Lsz + j];
    __syncthreads();

    float ent = 0.f, dif = 0.f;
    int cnt = 0;
    for (int j = tid; j < Lsz; j += 256) {
        float p = zs[j];
        ent += -(p * logf(__fadd_rn(p, 1e-7f)) +
                 (1.f - p) * logf(__fadd_rn(__fsub_rn(1.f, p), 1e-7f)));
        if (j < Lsz - 1) dif += fabsf(__fsub_rn(zs[j + 1], zs[j])) * g_adj[j];
        if (j < Ssz) {
            int tok = ids[(size_t)r * Ssz + j];
            if (p < 0.5f && tok != 0) cnt++;
        }
    }
    redf[tid] = ent; __syncthreads();
    for (int o = 128; o > 0; o >>= 1) { if (tid < o) redf[tid] += redf[tid + o]; __syncthreads(); }
    if (tid == 0) g_rowEnt[r] = redf[0];
    __syncthreads();
    redf[tid] = dif; __syncthreads();
    for (int o = 128; o > 0; o >>= 1) { if (tid < o) redf[tid] += redf[tid + o]; __syncthreads(); }
    if (tid == 0) g_rowDiff[r] = redf[0];
    __syncthreads();
    redi[tid] = cnt; __syncthreads();
    for (int o = 128; o > 0; o >>= 1) { if (tid < o) redi[tid] += redi[tid + o]; __syncthreads(); }
    const int total = redi[0];
    __syncthreads();
    const bool needfix = total > NEEDFIX_THRESH;

    unsigned int tsel = 0;
    int nEqKeep = 0;
    if (needfix) {
        unsigned int prefix = 0, highmask = 0;
        int k = MINTOK;
        for (int pass = 0; pass < 4; pass++) {
            const int shift = 24 - 8 * pass;
            hist[tid] = 0;
            __syncthreads();
            for (int j = tid; j < Ssz; j += 256) {
                unsigned int key = __float_as_uint(zs[j]);
                if ((key & highmask) == prefix)
                    atomicAdd(&hist[(key >> shift) & 0xFFu], 1u);
            }
            __syncthreads();
            if (tid == 0) {
                int cum = 0, b = 255;
                for (; b >= 0; --b) { cum += (int)hist[b]; if (cum >= k) break; }
                sh_k = k - (cum - (int)hist[b]);
                sh_prefix = prefix | ((unsigned int)b << shift);
            }
            __syncthreads();
            prefix = sh_prefix;
            k = sh_k;
            highmask |= 0xFFu << shift;
            __syncthreads();
        }
        tsel = prefix;
        int cg = 0;
        for (int j = tid; j < Ssz; j += 256)
            if (__float_as_uint(zs[j]) > tsel) cg++;
        redi[tid] = cg; __syncthreads();
        for (int o = 128; o > 0; o >>= 1) { if (tid < o) redi[tid] += redi[tid + o]; __syncthreads(); }
        nEqKeep = MINTOK - redi[0];
        __syncthreads();
    }

    int runEq = 0;
    for (int base = 0; base < Ssz; base += 256) {
        const int j = base + tid;
        const float zv = zs[j];
        const int tok = ids[(size_t)r * Ssz + j];
        bool m = (zv < 0.5f) && (tok != 0);
        if (needfix) {
            const unsigned int key = __float_as_uint(zv);
            const int eq = (key == tsel) ? 1 : 0;
            const unsigned int bal = __ballot_sync(0xffffffffu, eq);
            const int lane = tid & 31, w = tid >> 5;
            const int wexcl = __popc(bal & ((1u << lane) - 1u));
            if (lane == 31) wsum[w] = __popc(bal);
            __syncthreads();
            int woff = 0;
            for (int i = 0; i < w; i++) woff += wsum[i];
            const int excl = woff + wexcl;
            const bool keep = (key > tsel) || (eq && (runEq + excl) < nEqKeep);
            if (keep) m = false;
            __syncthreads();
            if (tid == 0) { int t = 0; for (int i = 0; i < 8; i++) t += wsum[i]; redi[0] = t; }
            __syncthreads();
            runEq += redi[0];
        }
        if (j == 0) m = false;
        outG[(size_t)r * Ssz + j] = m ? 0.f : (float)tok;
        outZ[(size_t)r * Ssz + j] = zv;
    }
}

// ---------------- final loss scalar -----------------------------------------
__global__ void finalize_kernel(float* __restrict__ out)
{
    __shared__ double red[256];
    const int tid = threadIdx.x;
    double e = 0, d = 0;
    for (int r = tid; r < Bsz; r += 256) {
        e += (double)g_rowEnt[r];
        d += (double)g_rowDiff[r];
    }
    red[tid] = e; __syncthreads();
    for (int o = 128; o > 0; o >>= 1) { if (tid < o) red[tid] += red[tid + o]; __syncthreads(); }
    const double entSum = red[0];
    __syncthreads();
    red[tid] = d; __syncthreads();
    for (int o = 128; o > 0; o >>= 1) { if (tid < o) red[tid] += red[tid + o]; __syncthreads(); }
    const double difSum = red[0];
    if (tid == 0) {
        double R1 = -0.001 * entSum / ((double)Bsz * (double)Lsz);
        double R2 =  0.001 * difSum / ((double)Bsz * (double)(Lsz - 1));
        double cons = 0.001 * g_cons[0] / (double)Lsz;
        out[(size_t)Bsz * Ssz] = (float)(R1 + R2 + cons);
    }
}

// ---------------- launch ------------------------------------------------------
extern "C" void kernel_launch(void* const* d_in, const int* in_sizes, int n_in,
                              void* d_out, int out_size)
{
    const float* in_g  = (const float*)d_in[0];
    const float* in_b  = (const float*)d_in[1];
    const float* wv    = (const float*)d_in[2];
    const float* bv    = (const float*)d_in[3];
    const float* wo    = (const float*)d_in[4];
    const float* bo    = (const float*)d_in[5];
    const float* w2    = (const float*)d_in[6];
    const float* b2    = (const float*)d_in[7];
    const float* g1    = (const float*)d_in[8];
    const float* be1   = (const float*)d_in[9];
    const float* w4    = (const float*)d_in[10];
    const float* b4    = (const float*)d_in[11];
    const float* g3    = (const float*)d_in[12];
    const float* be3   = (const float*)d_in[13];
    const float* w5    = (const float*)d_in[14];
    const float* b5    = (const float*)d_in[15];
    const float* g4    = (const float*)d_in[16];
    const float* be4   = (const float*)d_in[17];
    const float* w6    = (const float*)d_in[18];
    const float* b6    = (const float*)d_in[19];
    const float* g5    = (const float*)d_in[20];
    const float* be5   = (const float*)d_in[21];
    const float* w7    = (const float*)d_in[22];
    const float* b7    = (const float*)d_in[23];
    const float* g6    = (const float*)d_in[24];
    const float* be6   = (const float*)d_in[25];
    const float* wout  = (const float*)d_in[26];
    const float* bout  = (const float*)d_in[27];
    const float* fe    = (const float*)d_in[28];
    const int*   ids   = (const int*)d_in[29];
    float* out = (float*)d_out;

    float *pA, *pBf, *pC1, *pC2, *pC3, *pD1, *pD2;
    cudaGetSymbolAddress((void**)&pA,  g_A);
    cudaGetSymbolAddress((void**)&pBf, g_Bf);
    cudaGetSymbolAddress((void**)&pC1, g_C1);
    cudaGetSymbolAddress((void**)&pC2, g_C2);
    cudaGetSymbolAddress((void**)&pC3, g_C3);
    cudaGetSymbolAddress((void**)&pD1, g_D1);
    cudaGetSymbolAddress((void**)&pD2, g_D2);

    ln_input_kernel<<<Bsz, 256>>>(ids, in_g, in_b, pA);

    sgemm_nt<<<dim3(Lsz/64, Bsz/128), 256>>>(pA,  wv, bv, pBf, Bsz, Lsz, Lsz);
    sgemm_nt<<<dim3(Lsz/64, Bsz/128), 256>>>(pBf, wo, bo, pA,  Bsz, Lsz, Lsz);

    sgemm_nt<<<dim3(Hsz/64, Bsz/128), 256>>>(pA, w2, b2, pC1, Bsz, Hsz, Lsz);
    ln_gelu_kernel<<<Bsz, 256>>>(pC1, g1, be1, pC1, pC2, Hsz);

    sgemm_nt<<<dim3(Hsz/64, Bsz/128), 256>>>(pC2, w4, b4, pC3, Bsz, Hsz, Hsz);
    ln_gelu_kernel<<<Bsz, 256>>>(pC3, g3, be3, nullptr, pC3, Hsz);

    sgemm_nt<<<dim3(Hsz/64, Bsz/128), 256>>>(pC3, w5, b5, pC1, Bsz, Hsz, Hsz);
    ln_gelu_kernel<<<Bsz, 256>>>(pC1, g4, be4, pC2, pC1, Hsz);

    sgemm_nt<<<dim3((Hsz/2)/64, Bsz/128), 256>>>(pC1, w6, b6, pD1, Bsz, Hsz/2, Hsz);
    ln_gelu_kernel<<<Bsz, 256>>>(pD1, g5, be5, nullptr, pD1, Hsz/2);

    sgemm_nt<<<dim3((Hsz/4)/64, Bsz/128), 256>>>(pD1, w7, b7, pD2, Bsz, Hsz/4, Hsz/2);
    ln_gelu_kernel<<<Bsz, 256>>>(pD2, g6, be6, nullptr, pD2, Hsz/4);

    sgemm_nt<<<dim3(Lsz/64, Bsz/128), 256>>>(pD2, wout, bout, pBf, Bsz, Lsz, Hsz/4);
    sigmoid_kernel<<<(Bsz*Lsz)/256, 256>>>(pBf, pA);

    colstats_kernel<<<dim3(Lsz/256, CCH), 256>>>(pA);
    colcombine_kernel<<<Lsz/256, 256>>>();
    adjcons_kernel<<<1, 256>>>(fe);

    rowmask_kernel<<<Bsz, 256>>>(pA, ids, out, out + (size_t)Bsz * Ssz + 1);

    finalize_kernel<<<1, 256>>>(out);
}